// round 10
// baseline (speedup 1.0000x reference)
#include <cuda_runtime.h>
#include <math_constants.h>

// Problem constants (fixed shapes from setup_inputs)
#define BB   8      // batch
#define NPTS 256    // N = 4096/16
#define BETA 192    // 0.75*N
#define KN   768    // 3*N oversampled points
#define CO   128    // out channels
#define HO   256
#define WO   256
#define CF   64     // res2 channels
#define HF   512
#define WF   512
#define CFEAT (CO + CF)   // 192

__device__ float g_unc[BB * KN];
__device__ __align__(16) float g_featT[BB * CFEAT * NPTS];   // [B, 192, N]

#define PACK_F32X2(out, lo, hi) \
    asm("mov.b64 %0, {%1, %2};" : "=l"(out) : "f"(lo), "f"(hi))
#define FFMA2(acc, a, b) \
    asm("fma.rn.f32x2 %0, %1, %2, %0;" : "+l"(acc) : "l"(a), "l"(b))

// select element d (0..3) of a float4; d is warp-uniform small int
__device__ __forceinline__ float pick4(float4 q, int d) {
    float v = (d == 1) ? q.y : q.x;
    v = (d == 2) ? q.z : v;
    v = (d == 3) ? q.w : v;
    return v;
}

// merge running top2 (m1>=m2) with single value v
__device__ __forceinline__ void merge1(float &m1, float &m2, float v) {
    float n1 = fmaxf(m1, v);
    m2 = fmaxf(fminf(m1, v), m2);
    m1 = n1;
}
// merge running top2 with another pair (o1>=o2)
__device__ __forceinline__ void merge2(float &m1, float &m2, float o1, float o2) {
    float n1 = fmaxf(m1, o1);
    float n2 = fmaxf(fminf(m1, o1), fmaxf(m2, o2));
    m1 = n1; m2 = n2;
}

// ---------------------------------------------------------------------------
// Kernel 1: per-point uncertainty. One warp per point; x-corner pair fetched
// with one aligned float4 (plus warp-uniform extra load in the 12.5% case).
// ---------------------------------------------------------------------------
__global__ void uncert_kernel(const float* __restrict__ outm,
                              const float* __restrict__ rand_over) {
    int warp = (blockIdx.x * blockDim.x + threadIdx.x) >> 5;
    int lane = threadIdx.x & 31;
    if (warp >= BB * KN) return;
    int b = warp / KN;
    int p = warp - b * KN;

    float px = rand_over[(b * KN + p) * 2 + 0];
    float py = rand_over[(b * KN + p) * 2 + 1];
    float gx = px * (float)WO - 0.5f;
    float gy = py * (float)HO - 0.5f;
    float x0f = floorf(gx), y0f = floorf(gy);
    float wx = gx - x0f, wy = gy - y0f;
    int x0 = (int)x0f, y0 = (int)y0f;

    const float* base = outm + (long long)b * CO * HO * WO;
    bool xv0 = (x0 >= 0) && (x0 < WO);
    bool xv1 = (x0 + 1 >= 0) && (x0 + 1 < WO);
    bool yv0 = (y0 >= 0) && (y0 < HO);
    bool yv1 = (y0 + 1 >= 0) && (y0 + 1 < HO);
    int xc0 = min(max(x0, 0), WO - 1);
    int xc1 = min(max(x0 + 1, 0), WO - 1);
    int yc0 = min(max(y0, 0), HO - 1);
    int yc1 = min(max(y0 + 1, 0), HO - 1);

    int bx = xc0 & ~3;          // aligned float4 base
    int d0 = xc0 - bx;          // 0..3
    int d1 = xc1 - bx;          // 0..4 (4 => crosses into next float4)
    bool extra = (d1 == 4);     // warp-uniform

    const float* r0 = base + yc0 * WO;
    const float* r1 = base + yc1 * WO;

    // batched loads: 8 float4 (2 rows x 4 channel chunks), high MLP
    float4 q0[4], q1[4];
#pragma unroll
    for (int cc = 0; cc < 4; cc++) {
        long long co = (long long)(lane + cc * 32) * (HO * WO);
        q0[cc] = __ldg(reinterpret_cast<const float4*>(r0 + co + bx));
        q1[cc] = __ldg(reinterpret_cast<const float4*>(r1 + co + bx));
    }
    float vb0[4], vb1[4];
    if (extra) {
#pragma unroll
        for (int cc = 0; cc < 4; cc++) {
            long long co = (long long)(lane + cc * 32) * (HO * WO);
            vb0[cc] = __ldg(r0 + co + xc1);
            vb1[cc] = __ldg(r1 + co + xc1);
        }
    } else {
#pragma unroll
        for (int cc = 0; cc < 4; cc++) {
            vb0[cc] = pick4(q0[cc], d1);
            vb1[cc] = pick4(q1[cc], d1);
        }
    }

    float a1 = -CUDART_INF_F, a2 = -CUDART_INF_F;   // (y0,   x0)
    float b1 = -CUDART_INF_F, b2 = -CUDART_INF_F;   // (y0,   x0+1)
    float c1 = -CUDART_INF_F, c2 = -CUDART_INF_F;   // (y0+1, x0)
    float d1v = -CUDART_INF_F, d2v = -CUDART_INF_F; // (y0+1, x0+1)
#pragma unroll
    for (int cc = 0; cc < 4; cc++) {
        merge1(a1, a2, pick4(q0[cc], d0));
        merge1(b1, b2, vb0[cc]);
        merge1(c1, c2, pick4(q1[cc], d0));
        merge1(d1v, d2v, vb1[cc]);
    }
#pragma unroll
    for (int off = 16; off; off >>= 1) {
        merge2(a1, a2, __shfl_xor_sync(0xFFFFFFFFu, a1, off),
                       __shfl_xor_sync(0xFFFFFFFFu, a2, off));
        merge2(b1, b2, __shfl_xor_sync(0xFFFFFFFFu, b1, off),
                       __shfl_xor_sync(0xFFFFFFFFu, b2, off));
        merge2(c1, c2, __shfl_xor_sync(0xFFFFFFFFu, c1, off),
                       __shfl_xor_sync(0xFFFFFFFFu, c2, off));
        merge2(d1v, d2v, __shfl_xor_sync(0xFFFFFFFFu, d1v, off),
                         __shfl_xor_sync(0xFFFFFFFFu, d2v, off));
    }
    float e00 = (yv0 && xv0) ? (a2 - a1) : 0.f;   // -(top1 - top2), zero padded
    float e01 = (yv0 && xv1) ? (b2 - b1) : 0.f;
    float e10 = (yv1 && xv0) ? (c2 - c1) : 0.f;
    float e11 = (yv1 && xv1) ? (d2v - d1v) : 0.f;
    float unc = (1.f - wy) * ((1.f - wx) * e00 + wx * e01)
              +        wy  * ((1.f - wx) * e10 + wx * e11);
    if (lane == 0) g_unc[b * KN + p] = unc;
}

// ---------------------------------------------------------------------------
// Kernel 2: exact top-192 per batch; register-resident bitonic, shfl stages
// ---------------------------------------------------------------------------
__global__ void topk_kernel(const float* __restrict__ rand_over,
                            const float* __restrict__ rand_cov,
                            float* __restrict__ points) {
    int b = blockIdx.x;
    int t = threadIdx.x;
    __shared__ unsigned long long sk[1024];

    unsigned long long key = 0ull;  // pad: sorts last (real keys have high word > 0)
    if (t < KN) {
        float u = g_unc[b * KN + t];
        unsigned ub = __float_as_uint(u);
        ub = (ub & 0x80000000u) ? ~ub : (ub | 0x80000000u);  // total order
        key = ((unsigned long long)ub << 32) | (unsigned long long)(0xFFFFFFFFu - (unsigned)t);
    }

    for (int k = 2; k <= 1024; k <<= 1) {
        for (int j = k >> 1; j; j >>= 1) {
            unsigned long long other;
            if (j >= 32) {
                __syncthreads();
                sk[t] = key;
                __syncthreads();
                other = sk[t ^ j];
            } else {
                other = __shfl_xor_sync(0xFFFFFFFFu, key, j);
            }
            bool iLower = ((t & j) == 0);
            bool desc   = ((t & k) == 0);
            unsigned long long mx = (key > other) ? key : other;
            unsigned long long mn = (key > other) ? other : key;
            key = (desc == iLower) ? mx : mn;   // overall descending
        }
    }

    if (t < BETA) {
        unsigned idx = 0xFFFFFFFFu - (unsigned)(key & 0xFFFFFFFFull);
        points[(b * NPTS + t) * 2 + 0] = rand_over[(b * KN + idx) * 2 + 0];
        points[(b * NPTS + t) * 2 + 1] = rand_over[(b * KN + idx) * 2 + 1];
    } else if (t < NPTS) {
        int i = t - BETA;
        points[(b * NPTS + t) * 2 + 0] = rand_cov[(b * (NPTS - BETA) + i) * 2 + 0];
        points[(b * NPTS + t) * 2 + 1] = rand_cov[(b * (NPTS - BETA) + i) * 2 + 1];
    }
}

// ---------------------------------------------------------------------------
// Kernel 3: gather coarse(128)+fine(64) at each point -> transposed g_featT
// block per (batch, point), 192 threads; x-corner pair via aligned float4
// ---------------------------------------------------------------------------
__device__ __forceinline__ float bilerp_sample(const float* __restrict__ base,
                                               int H, int W, float px, float py) {
    float gx = px * (float)W - 0.5f;
    float gy = py * (float)H - 0.5f;
    float x0f = floorf(gx), y0f = floorf(gy);
    float wx = gx - x0f, wy = gy - y0f;
    int x0 = (int)x0f, y0 = (int)y0f;
    bool xv0 = (x0 >= 0) && (x0 < W);
    bool xv1 = (x0 + 1 >= 0) && (x0 + 1 < W);
    bool yv0 = (y0 >= 0) && (y0 < H);
    bool yv1 = (y0 + 1 >= 0) && (y0 + 1 < H);
    int xc0 = min(max(x0, 0), W - 1);
    int xc1 = min(max(x0 + 1, 0), W - 1);
    int yc0 = min(max(y0, 0), H - 1);
    int yc1 = min(max(y0 + 1, 0), H - 1);

    int bx = xc0 & ~3;
    int d0 = xc0 - bx;
    int d1 = xc1 - bx;
    const float* r0 = base + yc0 * W;
    const float* r1 = base + yc1 * W;
    float4 qa = __ldg(reinterpret_cast<const float4*>(r0 + bx));
    float4 qb = __ldg(reinterpret_cast<const float4*>(r1 + bx));
    float v00 = pick4(qa, d0);
    float v10 = pick4(qb, d0);
    float v01, v11;
    if (d1 == 4) {                       // warp-uniform (lanes share the point)
        v01 = __ldg(r0 + xc1);
        v11 = __ldg(r1 + xc1);
    } else {
        v01 = pick4(qa, d1);
        v11 = pick4(qb, d1);
    }
    v00 = (yv0 && xv0) ? v00 : 0.f;
    v01 = (yv0 && xv1) ? v01 : 0.f;
    v10 = (yv1 && xv0) ? v10 : 0.f;
    v11 = (yv1 && xv1) ? v11 : 0.f;
    return v00 * (1.f - wx) * (1.f - wy) + v01 * wx * (1.f - wy)
         + v10 * (1.f - wx) * wy + v11 * wx * wy;
}

__global__ void gather_kernel(const float* __restrict__ outm,
                              const float* __restrict__ res2,
                              const float* __restrict__ points) {
    int bp = blockIdx.x;
    int b = bp / NPTS;
    int n = bp - b * NPTS;
    int t = threadIdx.x;

    float px = points[bp * 2 + 0];
    float py = points[bp * 2 + 1];

    float v;
    if (t < CO) {
        const float* base = outm + ((long long)(b * CO + t)) * (HO * WO);
        v = bilerp_sample(base, HO, WO, px, py);
    } else {
        const float* base = res2 + ((long long)(b * CF + (t - CO))) * (HF * WF);
        v = bilerp_sample(base, HF, WF, px, py);
    }
    g_featT[((long long)b * CFEAT + t) * NPTS + n] = v;
}

// ---------------------------------------------------------------------------
// Kernel 4: rend[b,o,n] = weight[o,:] . featT[b,:,n] + bias[o]
// Massively parallel, no smem: 256 blocks x 256 threads, thread = 1 o x 4 n.
// Warp = one o (uniform weight loads), lane = 4 consecutive n (coalesced f).
// ---------------------------------------------------------------------------
__global__ __launch_bounds__(256) void gemm_kernel(
        const float* __restrict__ weight,
        const float* __restrict__ bias,
        float* __restrict__ rend) {
    int blk = blockIdx.x;               // = ((b*16 + ot)*2 + nt)
    int nt =  blk & 1;
    int ot = (blk >> 1) & 15;
    int b  =  blk >> 5;
    int wrp = threadIdx.x >> 5;         // 0..7
    int lane = threadIdx.x & 31;

    int o = ot * 8 + wrp;               // 0..127
    int n = nt * 128 + lane * 4;        // 0..255

    const float4* wr = reinterpret_cast<const float4*>(weight + o * CFEAT);
    const float* fb = g_featT + (long long)b * CFEAT * NPTS + n;

    unsigned long long acc0 = 0ull, acc1 = 0ull;
#pragma unroll
    for (int i = 0; i < CFEAT / 4; i++) {
        float4 w4 = __ldg(&wr[i]);      // warp-uniform 16B load
#pragma unroll
        for (int kk = 0; kk < 4; kk++) {
            float wv = (kk == 0) ? w4.x : (kk == 1) ? w4.y : (kk == 2) ? w4.z : w4.w;
            unsigned long long wp;
            PACK_F32X2(wp, wv, wv);
            const ulonglong2 ff = *reinterpret_cast<const ulonglong2*>(
                fb + (long long)(i * 4 + kk) * NPTS);
            FFMA2(acc0, wp, ff.x);
            FFMA2(acc1, wp, ff.y);
        }
    }

    float bv = bias[o];
    float4 outv;
    outv.x = __uint_as_float((unsigned)(acc0 & 0xFFFFFFFFull)) + bv;
    outv.y = __uint_as_float((unsigned)(acc0 >> 32)) + bv;
    outv.z = __uint_as_float((unsigned)(acc1 & 0xFFFFFFFFull)) + bv;
    outv.w = __uint_as_float((unsigned)(acc1 >> 32)) + bv;
    *reinterpret_cast<float4*>(rend + ((long long)b * CO + o) * NPTS + n) = outv;
}

// ---------------------------------------------------------------------------
// Launch
// ---------------------------------------------------------------------------
extern "C" void kernel_launch(void* const* d_in, const int* in_sizes, int n_in,
                              void* d_out, int out_size) {
    // metadata order: x, res2, out, rand_over, rand_cov, weight, bias
    const float* res2      = (const float*)d_in[1];
    const float* outm      = (const float*)d_in[2];
    const float* rand_over = (const float*)d_in[3];
    const float* rand_cov  = (const float*)d_in[4];
    const float* weight    = (const float*)d_in[5];
    const float* bias      = (const float*)d_in[6];

    float* rend   = (float*)d_out;                       // [B,128,256]
    float* points = (float*)d_out + BB * CO * NPTS;      // [B,256,2]

    uncert_kernel<<<(BB * KN) / 8, 256>>>(outm, rand_over);
    topk_kernel<<<BB, 1024>>>(rand_over, rand_cov, points);
    gather_kernel<<<BB * NPTS, CFEAT>>>(outm, res2, points);
    gemm_kernel<<<BB * 32, 256>>>(weight, bias, rend);
}

// round 11
// speedup vs baseline: 1.1704x; 1.1704x over previous
#include <cuda_runtime.h>
#include <math_constants.h>

// Problem constants (fixed shapes from setup_inputs)
#define BB   8      // batch
#define NPTS 256    // N = 4096/16
#define BETA 192    // 0.75*N
#define KN   768    // 3*N oversampled points
#define CO   128    // out channels
#define HO   256
#define WO   256
#define CF   64     // res2 channels
#define HF   512
#define WF   512
#define CFEAT (CO + CF)   // 192
#define RPTS 4            // points per render block

__device__ float g_unc[BB * KN];

#define PACK_F32X2(out, lo, hi) \
    asm("mov.b64 %0, {%1, %2};" : "=l"(out) : "f"(lo), "f"(hi))
#define FFMA2(acc, a, b) \
    asm("fma.rn.f32x2 %0, %1, %2, %0;" : "+l"(acc) : "l"(a), "l"(b))

// select element d (0..3) of a float4; d is warp-uniform small int
__device__ __forceinline__ float pick4(float4 q, int d) {
    float v = (d == 1) ? q.y : q.x;
    v = (d == 2) ? q.z : v;
    v = (d == 3) ? q.w : v;
    return v;
}

// merge running top2 (m1>=m2) with single value v
__device__ __forceinline__ void merge1(float &m1, float &m2, float v) {
    float n1 = fmaxf(m1, v);
    m2 = fmaxf(fminf(m1, v), m2);
    m1 = n1;
}
// merge running top2 with another pair (o1>=o2)
__device__ __forceinline__ void merge2(float &m1, float &m2, float o1, float o2) {
    float n1 = fmaxf(m1, o1);
    float n2 = fmaxf(fminf(m1, o1), fmaxf(m2, o2));
    m1 = n1; m2 = n2;
}

// ---------------------------------------------------------------------------
// Kernel 1: per-point uncertainty. One warp per point; x-corner pair fetched
// with one aligned float4 (plus warp-uniform extra load in the 12.5% case).
// ---------------------------------------------------------------------------
__global__ void uncert_kernel(const float* __restrict__ outm,
                              const float* __restrict__ rand_over) {
    int warp = (blockIdx.x * blockDim.x + threadIdx.x) >> 5;
    int lane = threadIdx.x & 31;
    if (warp >= BB * KN) return;
    int b = warp / KN;
    int p = warp - b * KN;

    float px = rand_over[(b * KN + p) * 2 + 0];
    float py = rand_over[(b * KN + p) * 2 + 1];
    float gx = px * (float)WO - 0.5f;
    float gy = py * (float)HO - 0.5f;
    float x0f = floorf(gx), y0f = floorf(gy);
    float wx = gx - x0f, wy = gy - y0f;
    int x0 = (int)x0f, y0 = (int)y0f;

    const float* base = outm + (long long)b * CO * HO * WO;
    bool xv0 = (x0 >= 0) && (x0 < WO);
    bool xv1 = (x0 + 1 >= 0) && (x0 + 1 < WO);
    bool yv0 = (y0 >= 0) && (y0 < HO);
    bool yv1 = (y0 + 1 >= 0) && (y0 + 1 < HO);
    int xc0 = min(max(x0, 0), WO - 1);
    int xc1 = min(max(x0 + 1, 0), WO - 1);
    int yc0 = min(max(y0, 0), HO - 1);
    int yc1 = min(max(y0 + 1, 0), HO - 1);

    int bx = xc0 & ~3;          // aligned float4 base
    int d0 = xc0 - bx;          // 0..3
    int d1 = xc1 - bx;          // 0..4 (4 => crosses into next float4)
    bool extra = (d1 == 4);     // warp-uniform

    const float* r0 = base + yc0 * WO;
    const float* r1 = base + yc1 * WO;

    // batched loads: 8 float4 (2 rows x 4 channel chunks), high MLP
    float4 q0[4], q1[4];
#pragma unroll
    for (int cc = 0; cc < 4; cc++) {
        long long co = (long long)(lane + cc * 32) * (HO * WO);
        q0[cc] = __ldg(reinterpret_cast<const float4*>(r0 + co + bx));
        q1[cc] = __ldg(reinterpret_cast<const float4*>(r1 + co + bx));
    }
    float vb0[4], vb1[4];
    if (extra) {
#pragma unroll
        for (int cc = 0; cc < 4; cc++) {
            long long co = (long long)(lane + cc * 32) * (HO * WO);
            vb0[cc] = __ldg(r0 + co + xc1);
            vb1[cc] = __ldg(r1 + co + xc1);
        }
    } else {
#pragma unroll
        for (int cc = 0; cc < 4; cc++) {
            vb0[cc] = pick4(q0[cc], d1);
            vb1[cc] = pick4(q1[cc], d1);
        }
    }

    float a1 = -CUDART_INF_F, a2 = -CUDART_INF_F;   // (y0,   x0)
    float b1 = -CUDART_INF_F, b2 = -CUDART_INF_F;   // (y0,   x0+1)
    float c1 = -CUDART_INF_F, c2 = -CUDART_INF_F;   // (y0+1, x0)
    float d1v = -CUDART_INF_F, d2v = -CUDART_INF_F; // (y0+1, x0+1)
#pragma unroll
    for (int cc = 0; cc < 4; cc++) {
        merge1(a1, a2, pick4(q0[cc], d0));
        merge1(b1, b2, vb0[cc]);
        merge1(c1, c2, pick4(q1[cc], d0));
        merge1(d1v, d2v, vb1[cc]);
    }
#pragma unroll
    for (int off = 16; off; off >>= 1) {
        merge2(a1, a2, __shfl_xor_sync(0xFFFFFFFFu, a1, off),
                       __shfl_xor_sync(0xFFFFFFFFu, a2, off));
        merge2(b1, b2, __shfl_xor_sync(0xFFFFFFFFu, b1, off),
                       __shfl_xor_sync(0xFFFFFFFFu, b2, off));
        merge2(c1, c2, __shfl_xor_sync(0xFFFFFFFFu, c1, off),
                       __shfl_xor_sync(0xFFFFFFFFu, c2, off));
        merge2(d1v, d2v, __shfl_xor_sync(0xFFFFFFFFu, d1v, off),
                         __shfl_xor_sync(0xFFFFFFFFu, d2v, off));
    }
    float e00 = (yv0 && xv0) ? (a2 - a1) : 0.f;   // -(top1 - top2), zero padded
    float e01 = (yv0 && xv1) ? (b2 - b1) : 0.f;
    float e10 = (yv1 && xv0) ? (c2 - c1) : 0.f;
    float e11 = (yv1 && xv1) ? (d2v - d1v) : 0.f;
    float unc = (1.f - wy) * ((1.f - wx) * e00 + wx * e01)
              +        wy  * ((1.f - wx) * e10 + wx * e11);
    if (lane == 0) g_unc[b * KN + p] = unc;
}

// ---------------------------------------------------------------------------
// Kernel 2: exact top-192 per batch; register-resident bitonic, shfl stages
// ---------------------------------------------------------------------------
__global__ void topk_kernel(const float* __restrict__ rand_over,
                            const float* __restrict__ rand_cov,
                            float* __restrict__ points) {
    int b = blockIdx.x;
    int t = threadIdx.x;
    __shared__ unsigned long long sk[1024];

    unsigned long long key = 0ull;  // pad: sorts last (real keys have high word > 0)
    if (t < KN) {
        float u = g_unc[b * KN + t];
        unsigned ub = __float_as_uint(u);
        ub = (ub & 0x80000000u) ? ~ub : (ub | 0x80000000u);  // total order
        key = ((unsigned long long)ub << 32) | (unsigned long long)(0xFFFFFFFFu - (unsigned)t);
    }

    for (int k = 2; k <= 1024; k <<= 1) {
        for (int j = k >> 1; j; j >>= 1) {
            unsigned long long other;
            if (j >= 32) {
                __syncthreads();
                sk[t] = key;
                __syncthreads();
                other = sk[t ^ j];
            } else {
                other = __shfl_xor_sync(0xFFFFFFFFu, key, j);
            }
            bool iLower = ((t & j) == 0);
            bool desc   = ((t & k) == 0);
            unsigned long long mx = (key > other) ? key : other;
            unsigned long long mn = (key > other) ? other : key;
            key = (desc == iLower) ? mx : mn;   // overall descending
        }
    }

    if (t < BETA) {
        unsigned idx = 0xFFFFFFFFu - (unsigned)(key & 0xFFFFFFFFull);
        points[(b * NPTS + t) * 2 + 0] = rand_over[(b * KN + idx) * 2 + 0];
        points[(b * NPTS + t) * 2 + 1] = rand_over[(b * KN + idx) * 2 + 1];
    } else if (t < NPTS) {
        int i = t - BETA;
        points[(b * NPTS + t) * 2 + 0] = rand_cov[(b * (NPTS - BETA) + i) * 2 + 0];
        points[(b * NPTS + t) * 2 + 1] = rand_cov[(b * (NPTS - BETA) + i) * 2 + 1];
    }
}

// ---------------------------------------------------------------------------
// Kernel 3 (fused render): gather 4 points x 192 ch into fs, then
// rend[b,o,n] = sum_k w[o,k]*fs[k][n] + bias[o] with smem-staged weight.
// grid = BB*(NPTS/4) = 512 blocks, 256 threads.
// ---------------------------------------------------------------------------
__device__ __forceinline__ float bilerp_sample(const float* __restrict__ base,
                                               int H, int W, float px, float py) {
    float gx = px * (float)W - 0.5f;
    float gy = py * (float)H - 0.5f;
    float x0f = floorf(gx), y0f = floorf(gy);
    float wx = gx - x0f, wy = gy - y0f;
    int x0 = (int)x0f, y0 = (int)y0f;
    bool xv0 = (x0 >= 0) && (x0 < W);
    bool xv1 = (x0 + 1 >= 0) && (x0 + 1 < W);
    bool yv0 = (y0 >= 0) && (y0 < H);
    bool yv1 = (y0 + 1 >= 0) && (y0 + 1 < H);
    int xc0 = min(max(x0, 0), W - 1);
    int xc1 = min(max(x0 + 1, 0), W - 1);
    int yc0 = min(max(y0, 0), H - 1);
    int yc1 = min(max(y0 + 1, 0), H - 1);

    const float* r0 = base + yc0 * W;
    const float* r1 = base + yc1 * W;
    float v00 = __ldg(r0 + xc0);
    float v01 = __ldg(r0 + xc1);
    float v10 = __ldg(r1 + xc0);
    float v11 = __ldg(r1 + xc1);
    v00 = (yv0 && xv0) ? v00 : 0.f;
    v01 = (yv0 && xv1) ? v01 : 0.f;
    v10 = (yv1 && xv0) ? v10 : 0.f;
    v11 = (yv1 && xv1) ? v11 : 0.f;
    return v00 * (1.f - wx) * (1.f - wy) + v01 * wx * (1.f - wy)
         + v10 * (1.f - wx) * wy + v11 * wx * wy;
}

__global__ __launch_bounds__(256) void render_kernel(
        const float* __restrict__ outm,
        const float* __restrict__ res2,
        const float* __restrict__ weight,
        const float* __restrict__ bias,
        const float* __restrict__ points,
        float* __restrict__ rend) {
    __shared__ float ws[CO][33];                    // one 32-k chunk, 16.9 KB
    __shared__ __align__(8) float fs[CFEAT][RPTS];  // 3 KB

    int blk = blockIdx.x;
    int b  = blk / (NPTS / RPTS);
    int n0 = (blk % (NPTS / RPTS)) * RPTS;
    int t = threadIdx.x;

    // ---- phase 1: gather 4*192 = 768 samples, 3 per thread
#pragma unroll
    for (int it = 0; it < 3; it++) {
        int s = t + it * 256;
        int p = s / CFEAT;
        int k = s - p * CFEAT;
        float px = points[(b * NPTS + n0 + p) * 2 + 0];
        float py = points[(b * NPTS + n0 + p) * 2 + 1];
        float v;
        if (k < CO) {
            v = bilerp_sample(outm + ((long long)(b * CO + k)) * (HO * WO),
                              HO, WO, px, py);
        } else {
            v = bilerp_sample(res2 + ((long long)(b * CF + (k - CO))) * (HF * WF),
                              HF, WF, px, py);
        }
        fs[k][p] = v;
    }

    // ---- phase 2: GEMM with k-chunked smem weight
    int o = t & 127;          // out channel
    int g = t >> 7;           // n-pair: (2g, 2g+1); warp-uniform
    unsigned long long acc = 0ull;

#pragma unroll
    for (int kc = 0; kc < CFEAT / 32; kc++) {
        __syncthreads();
        // stage ws[o][0..31] = weight[o][kc*32 .. +31]; coalesced float4 loads
#pragma unroll
        for (int j = t; j < CO * 8; j += 256) {
            int row = j >> 3, part = j & 7;
            float4 w4 = __ldg(reinterpret_cast<const float4*>(
                weight + row * CFEAT + kc * 32 + part * 4));
            ws[row][part * 4 + 0] = w4.x;
            ws[row][part * 4 + 1] = w4.y;
            ws[row][part * 4 + 2] = w4.z;
            ws[row][part * 4 + 3] = w4.w;
        }
        __syncthreads();

#pragma unroll
        for (int j = 0; j < 32; j++) {
            int k = kc * 32 + j;
            float wv = ws[o][j];                     // conflict-free (pad 33)
            unsigned long long wp;
            PACK_F32X2(wp, wv, wv);
            unsigned long long fpair =
                *reinterpret_cast<const unsigned long long*>(&fs[k][2 * g]);  // broadcast
            FFMA2(acc, wp, fpair);
        }
    }

    float bv = bias[o];
    float2 outv;
    outv.x = __uint_as_float((unsigned)(acc & 0xFFFFFFFFull)) + bv;
    outv.y = __uint_as_float((unsigned)(acc >> 32)) + bv;
    *reinterpret_cast<float2*>(rend + ((long long)b * CO + o) * NPTS + n0 + 2 * g) = outv;
}

// ---------------------------------------------------------------------------
// Launch
// ---------------------------------------------------------------------------
extern "C" void kernel_launch(void* const* d_in, const int* in_sizes, int n_in,
                              void* d_out, int out_size) {
    // metadata order: x, res2, out, rand_over, rand_cov, weight, bias
    const float* res2      = (const float*)d_in[1];
    const float* outm      = (const float*)d_in[2];
    const float* rand_over = (const float*)d_in[3];
    const float* rand_cov  = (const float*)d_in[4];
    const float* weight    = (const float*)d_in[5];
    const float* bias      = (const float*)d_in[6];

    float* rend   = (float*)d_out;                       // [B,128,256]
    float* points = (float*)d_out + BB * CO * NPTS;      // [B,256,2]

    uncert_kernel<<<(BB * KN) / 8, 256>>>(outm, rand_over);
    topk_kernel<<<BB, 1024>>>(rand_over, rand_cov, points);
    render_kernel<<<BB * (NPTS / RPTS), 256>>>(outm, res2, weight, bias, points, rend);
}

// round 12
// speedup vs baseline: 1.2112x; 1.0348x over previous
#include <cuda_runtime.h>
#include <math_constants.h>

// Problem constants (fixed shapes from setup_inputs)
#define BB   8      // batch
#define NPTS 256    // N = 4096/16
#define BETA 192    // 0.75*N
#define KN   768    // 3*N oversampled points
#define CO   128    // out channels
#define HO   256
#define WO   256
#define CF   64     // res2 channels
#define HF   512
#define WF   512
#define CFEAT (CO + CF)   // 192
#define RPTS 8            // points per render block

__device__ float g_unc[BB * KN];

#define PACK_F32X2(out, lo, hi) \
    asm("mov.b64 %0, {%1, %2};" : "=l"(out) : "f"(lo), "f"(hi))
#define FFMA2(acc, a, b) \
    asm("fma.rn.f32x2 %0, %1, %2, %0;" : "+l"(acc) : "l"(a), "l"(b))

// merge running top2 (m1>=m2) with single value v
__device__ __forceinline__ void merge1(float &m1, float &m2, float v) {
    float n1 = fmaxf(m1, v);
    m2 = fmaxf(fminf(m1, v), m2);
    m1 = n1;
}
// merge running top2 with another pair (o1>=o2)
__device__ __forceinline__ void merge2(float &m1, float &m2, float o1, float o2) {
    float n1 = fmaxf(m1, o1);
    float n2 = fmaxf(fminf(m1, o1), fmaxf(m2, o2));
    m1 = n1; m2 = n2;
}

// ---------------------------------------------------------------------------
// Kernel 1: per-point uncertainty, 2 warps per point (one per bilinear row).
// Rows are separable: unc = sum_r wyr * ((1-wx)*e0_r + wx*e1_r).
// Block = 256 threads = 4 points. Grid = 1536 blocks -> 393K threads.
// ---------------------------------------------------------------------------
__global__ void uncert_kernel(const float* __restrict__ outm,
                              const float* __restrict__ rand_over) {
    __shared__ float part[4][2];
    int tid = threadIdx.x;
    int wrp = tid >> 5;
    int lane = tid & 31;
    int ptl = wrp >> 1;          // local point 0..3
    int r   = wrp & 1;           // bilinear row 0/1
    int idx = blockIdx.x * 4 + ptl;   // global b*KN + p
    int b = idx / KN;

    float px = rand_over[idx * 2 + 0];
    float py = rand_over[idx * 2 + 1];
    float gx = px * (float)WO - 0.5f;
    float gy = py * (float)HO - 0.5f;
    float x0f = floorf(gx), y0f = floorf(gy);
    float wx = gx - x0f, wy = gy - y0f;
    int x0 = (int)x0f, y0 = (int)y0f;

    const float* base = outm + (long long)b * CO * HO * WO;
    bool xv0 = (x0 >= 0) && (x0 < WO);
    bool xv1 = (x0 + 1 >= 0) && (x0 + 1 < WO);
    int xc0 = min(max(x0, 0), WO - 1);
    int xc1 = min(max(x0 + 1, 0), WO - 1);

    int y = y0 + r;
    bool yv = (y >= 0) && (y < HO);
    int yc = min(max(y, 0), HO - 1);
    const float* rp = base + yc * WO;

    // 8 scalar loads, batched for MLP
    float v0[4], v1[4];
#pragma unroll
    for (int cc = 0; cc < 4; cc++) {
        long long co = (long long)(lane + cc * 32) * (HO * WO);
        v0[cc] = __ldg(rp + co + xc0);
        v1[cc] = __ldg(rp + co + xc1);
    }

    float a1 = -CUDART_INF_F, a2 = -CUDART_INF_F;   // corner x0
    float b1 = -CUDART_INF_F, b2 = -CUDART_INF_F;   // corner x0+1
#pragma unroll
    for (int cc = 0; cc < 4; cc++) {
        merge1(a1, a2, v0[cc]);
        merge1(b1, b2, v1[cc]);
    }
#pragma unroll
    for (int off = 16; off; off >>= 1) {
        merge2(a1, a2, __shfl_xor_sync(0xFFFFFFFFu, a1, off),
                       __shfl_xor_sync(0xFFFFFFFFu, a2, off));
        merge2(b1, b2, __shfl_xor_sync(0xFFFFFFFFu, b1, off),
                       __shfl_xor_sync(0xFFFFFFFFu, b2, off));
    }
    float e0 = (yv && xv0) ? (a2 - a1) : 0.f;   // -(top1 - top2), zero padded
    float e1 = (yv && xv1) ? (b2 - b1) : 0.f;
    float wyr = r ? wy : (1.f - wy);
    if (lane == 0)
        part[ptl][r] = wyr * ((1.f - wx) * e0 + wx * e1);
    __syncthreads();
    if (r == 0 && lane == 0)
        g_unc[idx] = part[ptl][0] + part[ptl][1];
}

// ---------------------------------------------------------------------------
// Kernel 2: exact top-192 per batch; register-resident bitonic, shfl stages
// ---------------------------------------------------------------------------
__global__ void topk_kernel(const float* __restrict__ rand_over,
                            const float* __restrict__ rand_cov,
                            float* __restrict__ points) {
    int b = blockIdx.x;
    int t = threadIdx.x;
    __shared__ unsigned long long sk[1024];

    unsigned long long key = 0ull;  // pad: sorts last (real keys have high word > 0)
    if (t < KN) {
        float u = g_unc[b * KN + t];
        unsigned ub = __float_as_uint(u);
        ub = (ub & 0x80000000u) ? ~ub : (ub | 0x80000000u);  // total order
        key = ((unsigned long long)ub << 32) | (unsigned long long)(0xFFFFFFFFu - (unsigned)t);
    }

    for (int k = 2; k <= 1024; k <<= 1) {
        for (int j = k >> 1; j; j >>= 1) {
            unsigned long long other;
            if (j >= 32) {
                __syncthreads();
                sk[t] = key;
                __syncthreads();
                other = sk[t ^ j];
            } else {
                other = __shfl_xor_sync(0xFFFFFFFFu, key, j);
            }
            bool iLower = ((t & j) == 0);
            bool desc   = ((t & k) == 0);
            unsigned long long mx = (key > other) ? key : other;
            unsigned long long mn = (key > other) ? other : key;
            key = (desc == iLower) ? mx : mn;   // overall descending
        }
    }

    if (t < BETA) {
        unsigned idx = 0xFFFFFFFFu - (unsigned)(key & 0xFFFFFFFFull);
        points[(b * NPTS + t) * 2 + 0] = rand_over[(b * KN + idx) * 2 + 0];
        points[(b * NPTS + t) * 2 + 1] = rand_over[(b * KN + idx) * 2 + 1];
    } else if (t < NPTS) {
        int i = t - BETA;
        points[(b * NPTS + t) * 2 + 0] = rand_cov[(b * (NPTS - BETA) + i) * 2 + 0];
        points[(b * NPTS + t) * 2 + 1] = rand_cov[(b * (NPTS - BETA) + i) * 2 + 1];
    }
}

// ---------------------------------------------------------------------------
// Kernel 3 (fused render): gather 8 points x 192 ch into fs, then
// rend[b,o,n] = sum_k w[o,k]*fs[k][n] + bias[o] with smem-staged weight.
// grid = BB*(NPTS/8) = 256 blocks, 512 threads (all blocks resident at once).
// ---------------------------------------------------------------------------
__device__ __forceinline__ float bilerp_sample(const float* __restrict__ base,
                                               int H, int W, float px, float py) {
    float gx = px * (float)W - 0.5f;
    float gy = py * (float)H - 0.5f;
    float x0f = floorf(gx), y0f = floorf(gy);
    float wx = gx - x0f, wy = gy - y0f;
    int x0 = (int)x0f, y0 = (int)y0f;
    bool xv0 = (x0 >= 0) && (x0 < W);
    bool xv1 = (x0 + 1 >= 0) && (x0 + 1 < W);
    bool yv0 = (y0 >= 0) && (y0 < H);
    bool yv1 = (y0 + 1 >= 0) && (y0 + 1 < H);
    int xc0 = min(max(x0, 0), W - 1);
    int xc1 = min(max(x0 + 1, 0), W - 1);
    int yc0 = min(max(y0, 0), H - 1);
    int yc1 = min(max(y0 + 1, 0), H - 1);

    const float* r0 = base + yc0 * W;
    const float* r1 = base + yc1 * W;
    float v00 = __ldg(r0 + xc0);
    float v01 = __ldg(r0 + xc1);
    float v10 = __ldg(r1 + xc0);
    float v11 = __ldg(r1 + xc1);
    v00 = (yv0 && xv0) ? v00 : 0.f;
    v01 = (yv0 && xv1) ? v01 : 0.f;
    v10 = (yv1 && xv0) ? v10 : 0.f;
    v11 = (yv1 && xv1) ? v11 : 0.f;
    return v00 * (1.f - wx) * (1.f - wy) + v01 * wx * (1.f - wy)
         + v10 * (1.f - wx) * wy + v11 * wx * wy;
}

__global__ __launch_bounds__(512) void render_kernel(
        const float* __restrict__ outm,
        const float* __restrict__ res2,
        const float* __restrict__ weight,
        const float* __restrict__ bias,
        const float* __restrict__ points,
        float* __restrict__ rend) {
    __shared__ float ws[CO][33];                    // one 32-k chunk, 16.9 KB
    __shared__ __align__(8) float fs[CFEAT][RPTS];  // 6 KB

    int blk = blockIdx.x;
    int b  = blk / (NPTS / RPTS);
    int n0 = (blk % (NPTS / RPTS)) * RPTS;
    int t = threadIdx.x;

    // ---- phase 1: gather 8*192 = 1536 samples, 3 per thread
#pragma unroll
    for (int it = 0; it < 3; it++) {
        int s = t + it * 512;
        int p = s / CFEAT;
        int k = s - p * CFEAT;
        float px = points[(b * NPTS + n0 + p) * 2 + 0];
        float py = points[(b * NPTS + n0 + p) * 2 + 1];
        float v;
        if (k < CO) {
            v = bilerp_sample(outm + ((long long)(b * CO + k)) * (HO * WO),
                              HO, WO, px, py);
        } else {
            v = bilerp_sample(res2 + ((long long)(b * CF + (k - CO))) * (HF * WF),
                              HF, WF, px, py);
        }
        fs[k][p] = v;
    }

    // ---- phase 2: GEMM with k-chunked smem weight
    int o = t & 127;          // out channel
    int g = t >> 7;           // n-pair: (2g, 2g+1); warp-uniform
    unsigned long long acc = 0ull;

#pragma unroll
    for (int kc = 0; kc < CFEAT / 32; kc++) {
        __syncthreads();
        // stage ws[o][0..31] = weight[o][kc*32 .. +31]; coalesced float4 loads
#pragma unroll
        for (int j = t; j < CO * 8; j += 512) {
            int row = j >> 3, part = j & 7;
            float4 w4 = __ldg(reinterpret_cast<const float4*>(
                weight + row * CFEAT + kc * 32 + part * 4));
            ws[row][part * 4 + 0] = w4.x;
            ws[row][part * 4 + 1] = w4.y;
            ws[row][part * 4 + 2] = w4.z;
            ws[row][part * 4 + 3] = w4.w;
        }
        __syncthreads();

#pragma unroll
        for (int j = 0; j < 32; j++) {
            int k = kc * 32 + j;
            float wv = ws[o][j];                     // conflict-free (pad 33)
            unsigned long long wp;
            PACK_F32X2(wp, wv, wv);
            unsigned long long fpair =
                *reinterpret_cast<const unsigned long long*>(&fs[k][2 * g]);  // broadcast
            FFMA2(acc, wp, fpair);
        }
    }

    float bv = bias[o];
    float2 outv;
    outv.x = __uint_as_float((unsigned)(acc & 0xFFFFFFFFull)) + bv;
    outv.y = __uint_as_float((unsigned)(acc >> 32)) + bv;
    *reinterpret_cast<float2*>(rend + ((long long)b * CO + o) * NPTS + n0 + 2 * g) = outv;
}

// ---------------------------------------------------------------------------
// Launch
// ---------------------------------------------------------------------------
extern "C" void kernel_launch(void* const* d_in, const int* in_sizes, int n_in,
                              void* d_out, int out_size) {
    // metadata order: x, res2, out, rand_over, rand_cov, weight, bias
    const float* res2      = (const float*)d_in[1];
    const float* outm      = (const float*)d_in[2];
    const float* rand_over = (const float*)d_in[3];
    const float* rand_cov  = (const float*)d_in[4];
    const float* weight    = (const float*)d_in[5];
    const float* bias      = (const float*)d_in[6];

    float* rend   = (float*)d_out;                       // [B,128,256]
    float* points = (float*)d_out + BB * CO * NPTS;      // [B,256,2]

    // 2 warps per point (row-split), 4 points per 256-thread block
    uncert_kernel<<<(BB * KN) / 4, 256>>>(outm, rand_over);
    topk_kernel<<<BB, 1024>>>(rand_over, rand_cov, points);
    render_kernel<<<BB * (NPTS / RPTS), 512>>>(outm, res2, weight, bias, points, rend);
}

// round 13
// speedup vs baseline: 1.2506x; 1.0325x over previous
#include <cuda_runtime.h>
#include <math_constants.h>

// Problem constants (fixed shapes from setup_inputs)
#define BB   8      // batch
#define NPTS 256    // N = 4096/16
#define BETA 192    // 0.75*N
#define KN   768    // 3*N oversampled points
#define CO   128    // out channels
#define HO   256
#define WO   256
#define CF   64     // res2 channels
#define HF   512
#define WF   512
#define CFEAT (CO + CF)   // 192
#define RPTS 8            // points per render block

__device__ float g_unc[BB * KN];
__device__ __align__(16) float g_featC[BB * KN * CO];   // cached coarse features
__device__ int   g_idx[BB * BETA];                      // selected oversample idx

#define PACK_F32X2(out, lo, hi) \
    asm("mov.b64 %0, {%1, %2};" : "=l"(out) : "f"(lo), "f"(hi))
#define FFMA2(acc, a, b) \
    asm("fma.rn.f32x2 %0, %1, %2, %0;" : "+l"(acc) : "l"(a), "l"(b))

// merge running top2 (m1>=m2) with single value v
__device__ __forceinline__ void merge1(float &m1, float &m2, float v) {
    float n1 = fmaxf(m1, v);
    m2 = fmaxf(fminf(m1, v), m2);
    m1 = n1;
}
// merge running top2 with another pair (o1>=o2)
__device__ __forceinline__ void merge2(float &m1, float &m2, float o1, float o2) {
    float n1 = fmaxf(m1, o1);
    float n2 = fmaxf(fminf(m1, o1), fmaxf(m2, o2));
    m1 = n1; m2 = n2;
}

// ---------------------------------------------------------------------------
// Kernel 1: per-point uncertainty + coarse-feature cache.
// 2 warps per point (one per bilinear row); block = 4 points (256 thr).
// Each warp also computes per-channel x-blended row values; the two rows are
// summed through smem to yield point_sample(out, point) for all 128 channels.
// ---------------------------------------------------------------------------
__global__ void uncert_kernel(const float* __restrict__ outm,
                              const float* __restrict__ rand_over) {
    __shared__ float part[4][2];
    __shared__ float rv[4][2][CO];    // per-point, per-row channel blends (4 KB)
    int tid = threadIdx.x;
    int wrp = tid >> 5;
    int lane = tid & 31;
    int ptl = wrp >> 1;          // local point 0..3
    int r   = wrp & 1;           // bilinear row 0/1
    int idx = blockIdx.x * 4 + ptl;   // global b*KN + p
    int b = idx / KN;

    float px = rand_over[idx * 2 + 0];
    float py = rand_over[idx * 2 + 1];
    float gx = px * (float)WO - 0.5f;
    float gy = py * (float)HO - 0.5f;
    float x0f = floorf(gx), y0f = floorf(gy);
    float wx = gx - x0f, wy = gy - y0f;
    int x0 = (int)x0f, y0 = (int)y0f;

    const float* base = outm + (long long)b * CO * HO * WO;
    bool xv0 = (x0 >= 0) && (x0 < WO);
    bool xv1 = (x0 + 1 >= 0) && (x0 + 1 < WO);
    int xc0 = min(max(x0, 0), WO - 1);
    int xc1 = min(max(x0 + 1, 0), WO - 1);

    int y = y0 + r;
    bool yv = (y >= 0) && (y < HO);
    int yc = min(max(y, 0), HO - 1);
    const float* rp = base + yc * WO;
    float wyr = r ? wy : (1.f - wy);

    // 8 scalar loads, batched for MLP
    float v0[4], v1[4];
#pragma unroll
    for (int cc = 0; cc < 4; cc++) {
        long long co = (long long)(lane + cc * 32) * (HO * WO);
        v0[cc] = __ldg(rp + co + xc0);
        v1[cc] = __ldg(rp + co + xc1);
    }

    // per-channel x-blend with zero padding -> row contribution to the
    // bilinear sample of each raw channel (cached for render's coarse gather)
    float m0 = (yv && xv0) ? 1.f : 0.f;
    float m1 = (yv && xv1) ? 1.f : 0.f;
#pragma unroll
    for (int cc = 0; cc < 4; cc++) {
        rv[ptl][r][lane + cc * 32] =
            wyr * ((1.f - wx) * m0 * v0[cc] + wx * m1 * v1[cc]);
    }

    float a1 = -CUDART_INF_F, a2 = -CUDART_INF_F;   // corner x0
    float b1 = -CUDART_INF_F, b2 = -CUDART_INF_F;   // corner x0+1
#pragma unroll
    for (int cc = 0; cc < 4; cc++) {
        merge1(a1, a2, v0[cc]);
        merge1(b1, b2, v1[cc]);
    }
#pragma unroll
    for (int off = 16; off; off >>= 1) {
        merge2(a1, a2, __shfl_xor_sync(0xFFFFFFFFu, a1, off),
                       __shfl_xor_sync(0xFFFFFFFFu, a2, off));
        merge2(b1, b2, __shfl_xor_sync(0xFFFFFFFFu, b1, off),
                       __shfl_xor_sync(0xFFFFFFFFu, b2, off));
    }
    float e0 = (yv && xv0) ? (a2 - a1) : 0.f;   // -(top1 - top2), zero padded
    float e1 = (yv && xv1) ? (b2 - b1) : 0.f;
    if (lane == 0)
        part[ptl][r] = wyr * ((1.f - wx) * e0 + wx * e1);
    __syncthreads();

    if (r == 0 && lane == 0)
        g_unc[idx] = part[ptl][0] + part[ptl][1];

    // write cached coarse features: 4 pts x 128 ch, 2 entries per thread
#pragma unroll
    for (int it = 0; it < 2; it++) {
        int s = tid + it * 256;
        int pt = s >> 7;
        int c  = s & 127;
        g_featC[(long long)(blockIdx.x * 4 + pt) * CO + c] =
            rv[pt][0][c] + rv[pt][1][c];
    }
}

// ---------------------------------------------------------------------------
// Kernel 2: exact top-192 per batch; register-resident bitonic, shfl stages.
// Also records the selected oversample indices for the render lookup.
// ---------------------------------------------------------------------------
__global__ void topk_kernel(const float* __restrict__ rand_over,
                            const float* __restrict__ rand_cov,
                            float* __restrict__ points) {
    int b = blockIdx.x;
    int t = threadIdx.x;
    __shared__ unsigned long long sk[1024];

    unsigned long long key = 0ull;  // pad: sorts last (real keys have high word > 0)
    if (t < KN) {
        float u = g_unc[b * KN + t];
        unsigned ub = __float_as_uint(u);
        ub = (ub & 0x80000000u) ? ~ub : (ub | 0x80000000u);  // total order
        key = ((unsigned long long)ub << 32) | (unsigned long long)(0xFFFFFFFFu - (unsigned)t);
    }

    for (int k = 2; k <= 1024; k <<= 1) {
        for (int j = k >> 1; j; j >>= 1) {
            unsigned long long other;
            if (j >= 32) {
                __syncthreads();
                sk[t] = key;
                __syncthreads();
                other = sk[t ^ j];
            } else {
                other = __shfl_xor_sync(0xFFFFFFFFu, key, j);
            }
            bool iLower = ((t & j) == 0);
            bool desc   = ((t & k) == 0);
            unsigned long long mx = (key > other) ? key : other;
            unsigned long long mn = (key > other) ? other : key;
            key = (desc == iLower) ? mx : mn;   // overall descending
        }
    }

    if (t < BETA) {
        unsigned idx = 0xFFFFFFFFu - (unsigned)(key & 0xFFFFFFFFull);
        g_idx[b * BETA + t] = (int)idx;
        points[(b * NPTS + t) * 2 + 0] = rand_over[(b * KN + idx) * 2 + 0];
        points[(b * NPTS + t) * 2 + 1] = rand_over[(b * KN + idx) * 2 + 1];
    } else if (t < NPTS) {
        int i = t - BETA;
        points[(b * NPTS + t) * 2 + 0] = rand_cov[(b * (NPTS - BETA) + i) * 2 + 0];
        points[(b * NPTS + t) * 2 + 1] = rand_cov[(b * (NPTS - BETA) + i) * 2 + 1];
    }
}

// ---------------------------------------------------------------------------
// Kernel 3 (fused render): gather 8 points x 192 ch into fs (coarse features
// of importance points come from the g_featC cache), then GEMM with
// smem-staged weight. grid = 256 blocks, 512 threads.
// ---------------------------------------------------------------------------
__device__ __forceinline__ float bilerp_sample(const float* __restrict__ base,
                                               int H, int W, float px, float py) {
    float gx = px * (float)W - 0.5f;
    float gy = py * (float)H - 0.5f;
    float x0f = floorf(gx), y0f = floorf(gy);
    float wx = gx - x0f, wy = gy - y0f;
    int x0 = (int)x0f, y0 = (int)y0f;
    bool xv0 = (x0 >= 0) && (x0 < W);
    bool xv1 = (x0 + 1 >= 0) && (x0 + 1 < W);
    bool yv0 = (y0 >= 0) && (y0 < H);
    bool yv1 = (y0 + 1 >= 0) && (y0 + 1 < H);
    int xc0 = min(max(x0, 0), W - 1);
    int xc1 = min(max(x0 + 1, 0), W - 1);
    int yc0 = min(max(y0, 0), H - 1);
    int yc1 = min(max(y0 + 1, 0), H - 1);

    const float* r0 = base + yc0 * W;
    const float* r1 = base + yc1 * W;
    float v00 = __ldg(r0 + xc0);
    float v01 = __ldg(r0 + xc1);
    float v10 = __ldg(r1 + xc0);
    float v11 = __ldg(r1 + xc1);
    v00 = (yv0 && xv0) ? v00 : 0.f;
    v01 = (yv0 && xv1) ? v01 : 0.f;
    v10 = (yv1 && xv0) ? v10 : 0.f;
    v11 = (yv1 && xv1) ? v11 : 0.f;
    return v00 * (1.f - wx) * (1.f - wy) + v01 * wx * (1.f - wy)
         + v10 * (1.f - wx) * wy + v11 * wx * wy;
}

__global__ __launch_bounds__(512) void render_kernel(
        const float* __restrict__ outm,
        const float* __restrict__ res2,
        const float* __restrict__ weight,
        const float* __restrict__ bias,
        const float* __restrict__ points,
        float* __restrict__ rend) {
    __shared__ float ws[CO][33];                    // one 32-k chunk, 16.9 KB
    __shared__ __align__(8) float fs[CFEAT][RPTS];  // 6 KB

    int blk = blockIdx.x;
    int b  = blk / (NPTS / RPTS);
    int n0 = (blk % (NPTS / RPTS)) * RPTS;
    int t = threadIdx.x;

    // ---- phase 1: gather 8*192 = 1536 samples, 3 per thread
#pragma unroll
    for (int it = 0; it < 3; it++) {
        int s = t + it * 512;
        int p = s / CFEAT;
        int k = s - p * CFEAT;
        int n = n0 + p;
        float v;
        if (k < CO) {
            if (n < BETA) {
                // importance point: cached bilinear coarse feature
                int gi = g_idx[b * BETA + n];
                v = __ldg(g_featC + (long long)(b * KN + gi) * CO + k);
            } else {
                float px = points[(b * NPTS + n) * 2 + 0];
                float py = points[(b * NPTS + n) * 2 + 1];
                v = bilerp_sample(outm + ((long long)(b * CO + k)) * (HO * WO),
                                  HO, WO, px, py);
            }
        } else {
            float px = points[(b * NPTS + n) * 2 + 0];
            float py = points[(b * NPTS + n) * 2 + 1];
            v = bilerp_sample(res2 + ((long long)(b * CF + (k - CO))) * (HF * WF),
                              HF, WF, px, py);
        }
        fs[k][p] = v;
    }

    // ---- phase 2: GEMM with k-chunked smem weight
    int o = t & 127;          // out channel
    int g = t >> 7;           // n-pair: (2g, 2g+1); warp-uniform
    unsigned long long acc = 0ull;

#pragma unroll
    for (int kc = 0; kc < CFEAT / 32; kc++) {
        __syncthreads();
        // stage ws[o][0..31] = weight[o][kc*32 .. +31]; coalesced float4 loads
#pragma unroll
        for (int j = t; j < CO * 8; j += 512) {
            int row = j >> 3, part = j & 7;
            float4 w4 = __ldg(reinterpret_cast<const float4*>(
                weight + row * CFEAT + kc * 32 + part * 4));
            ws[row][part * 4 + 0] = w4.x;
            ws[row][part * 4 + 1] = w4.y;
            ws[row][part * 4 + 2] = w4.z;
            ws[row][part * 4 + 3] = w4.w;
        }
        __syncthreads();

#pragma unroll
        for (int j = 0; j < 32; j++) {
            int k = kc * 32 + j;
            float wv = ws[o][j];                     // conflict-free (pad 33)
            unsigned long long wp;
            PACK_F32X2(wp, wv, wv);
            unsigned long long fpair =
                *reinterpret_cast<const unsigned long long*>(&fs[k][2 * g]);  // broadcast
            FFMA2(acc, wp, fpair);
        }
    }

    float bv = bias[o];
    float2 outv;
    outv.x = __uint_as_float((unsigned)(acc & 0xFFFFFFFFull)) + bv;
    outv.y = __uint_as_float((unsigned)(acc >> 32)) + bv;
    *reinterpret_cast<float2*>(rend + ((long long)b * CO + o) * NPTS + n0 + 2 * g) = outv;
}

// ---------------------------------------------------------------------------
// Launch
// ---------------------------------------------------------------------------
extern "C" void kernel_launch(void* const* d_in, const int* in_sizes, int n_in,
                              void* d_out, int out_size) {
    // metadata order: x, res2, out, rand_over, rand_cov, weight, bias
    const float* res2      = (const float*)d_in[1];
    const float* outm      = (const float*)d_in[2];
    const float* rand_over = (const float*)d_in[3];
    const float* rand_cov  = (const float*)d_in[4];
    const float* weight    = (const float*)d_in[5];
    const float* bias      = (const float*)d_in[6];

    float* rend   = (float*)d_out;                       // [B,128,256]
    float* points = (float*)d_out + BB * CO * NPTS;      // [B,256,2]

    // 2 warps per point (row-split), 4 points per 256-thread block
    uncert_kernel<<<(BB * KN) / 4, 256>>>(outm, rand_over);
    topk_kernel<<<BB, 1024>>>(rand_over, rand_cov, points);
    render_kernel<<<BB * (NPTS / RPTS), 512>>>(outm, res2, weight, bias, points, rend);
}